// round 8
// baseline (speedup 1.0000x reference)
#include <cuda_runtime.h>

// LocalExpansion via scatter, single-wave version.
// out[q, k, dv] = in[q + shift(k), dv] (7x7 window, zero-padded).
// Each thread handles the SAME (y, x, dv) slice for TWO batch-head planes
// (bh and bh+8), sharing all coordinate math and predicates. Grid is
// (3, 48, 8) = 1152 CTAs <= one full wave (152 SMs x 8 CTAs of 256 thr),
// so every SM is busy with identical work from start to finish - no tail.
//
// B*H = 16, N = 48*48 = 2304, K = 49, D = 64 floats (= 16 float4).

#define HEIGHT 48
#define WIDTH  48
#define NPIX   (HEIGHT * WIDTH)   // 2304
#define KK     49
#define DVEC   16                 // float4 per tap
#define ROWV   (KK * DVEC)        // 784 float4 per output pixel row
#define BH_FOLD 8                 // plane stride folded into each thread

__global__ void __launch_bounds__(256) local_scatter_wave_kernel(
    const float4* __restrict__ in, float4* __restrict__ out)
{
    // blockDim = 256 = 16 dv * 16 x-pixels ; gridDim = (3, 48, 8)
    const int dv = (int)(threadIdx.x & 15u);
    const int x  = (int)(blockIdx.x * 16u + (threadIdx.x >> 4));
    const int y  = (int)blockIdx.y;
    const int bh = (int)blockIdx.z;           // handles bh and bh + 8

    const unsigned int n  = (unsigned)(y * WIDTH + x);
    const unsigned int p0 = (unsigned)bh * NPIX + n;
    const unsigned int p1 = (unsigned)(bh + BH_FOLD) * NPIX + n;

    const float4 v0 = __ldg(in + (size_t)p0 * DVEC + dv);
    const float4 v1 = __ldg(in + (size_t)p1 * DVEC + dv);
    float4* __restrict__ b0 = out + (size_t)p0 * ROWV + dv;
    float4* __restrict__ b1 = out + (size_t)p1 * ROWV + dv;

    if ((unsigned)(y - 3) < (unsigned)(HEIGHT - 6) &&
        (unsigned)(x - 3) < (unsigned)(WIDTH - 6)) {
        // Interior: all 49 source and destination pixels valid.
        #pragma unroll
        for (int i = 0; i < 7; ++i) {
            #pragma unroll
            for (int j = 0; j < 7; ++j) {
                const int k = i * 7 + j;
                const int scat_off = -(((i - 3) * WIDTH) + (j - 3)) * ROWV + k * DVEC;
                __stcs(b0 + scat_off, v0);
                __stcs(b1 + scat_off, v1);
            }
        }
    } else {
        const float4 z = make_float4(0.f, 0.f, 0.f, 0.f);
        #pragma unroll
        for (int i = 0; i < 7; ++i) {
            const bool src_yok = (unsigned)(y + (i - 3)) < (unsigned)HEIGHT;
            const bool dst_yok = (unsigned)(y - (i - 3)) < (unsigned)HEIGHT;
            #pragma unroll
            for (int j = 0; j < 7; ++j) {
                const int k = i * 7 + j;
                const bool dst_ok = dst_yok && ((unsigned)(x - (j - 3)) < (unsigned)WIDTH);
                const bool src_ok = src_yok && ((unsigned)(x + (j - 3)) < (unsigned)WIDTH);

                const int scat_off = -(((i - 3) * WIDTH) + (j - 3)) * ROWV + k * DVEC;
                if (dst_ok) { __stcs(b0 + scat_off, v0); __stcs(b1 + scat_off, v1); }
                if (!src_ok) { __stcs(b0 + k * DVEC, z); __stcs(b1 + k * DVEC, z); }
            }
        }
    }
}

extern "C" void kernel_launch(void* const* d_in, const int* in_sizes, int n_in,
                              void* d_out, int out_size)
{
    const float4* in = (const float4*)d_in[0];
    float4* out = (float4*)d_out;
    (void)out_size;

    dim3 grid(WIDTH / 16, HEIGHT, BH_FOLD);   // (3, 48, 8) -> 1152 CTAs, one wave
    local_scatter_wave_kernel<<<grid, 256>>>(in, out);
}

// round 9
// speedup vs baseline: 1.0451x; 1.0451x over previous
#include <cuda_runtime.h>
#include <cstdint>

// LocalExpansion, SMEM-staged + bulk async store (UBLKCP), table-driven fill.
// Each CTA produces 2 consecutive output pixel-rows (2*49 taps * 256 B =
// 25088 B, contiguous in gmem). Phase 1: 98 threads compute the (pixel,tap)
// source offsets once (div chain runs 98x per CTA instead of 1568x).
// Phase 2: cheap fill loop (shift/mask + table lookup + LDG + STS).
// Phase 3: one cp.async.bulk shared->global for the 25 KB chunk.
//
// B*H = 16, N = 48*48 = 2304, K = 49, D = 64 floats (= 16 float4).

#define HEIGHT 48
#define WIDTH  48
#define NPIX   (HEIGHT * WIDTH)              // 2304
#define KK     49
#define DVEC   16                            // float4 per tap
#define CHUNK_PIX 2
#define CHUNK_ELEMS (CHUNK_PIX * KK * DVEC)  // 1568 float4
#define CHUNK_BYTES (CHUNK_ELEMS * 16)       // 25088
#define THREADS 256

__global__ void __launch_bounds__(THREADS) local_expand_bulk2_kernel(
    const float4* __restrict__ in, float4* __restrict__ out)
{
    __shared__ alignas(128) float4 tile[CHUNK_ELEMS];
    __shared__ int srcoff[CHUNK_PIX * KK];   // float4 index into `in`, -1 = OOB

    const unsigned int p0 = blockIdx.x * CHUNK_PIX;

    // Phase 1: per-(pixel,tap) source offsets, once per CTA.
    if (threadIdx.x < CHUNK_PIX * KK) {
        const unsigned int r  = threadIdx.x;          // pp*49 + k
        const unsigned int pp = (r >= KK) ? 1u : 0u;
        const unsigned int k  = r - KK * pp;
        const unsigned int p  = p0 + pp;
        const unsigned int n  = p % NPIX;
        const int y = (int)(n / WIDTH);
        const int x = (int)(n % WIDTH);
        const int i = (int)(k / 7);
        const int j = (int)(k % 7);
        const int sy = y + i - 3;
        const int sx = x + j - 3;
        int off = -1;
        if ((unsigned)sy < (unsigned)HEIGHT && (unsigned)sx < (unsigned)WIDTH)
            off = (int)(((p - n) + (unsigned)(sy * WIDTH + sx)) * DVEC);
        srcoff[r] = off;
    }
    __syncthreads();

    // Phase 2: cheap fill. 7 iterations, last partial (6*256=1536 < 1568).
    #pragma unroll
    for (int it = 0; it < 7; ++it) {
        const unsigned int idx = threadIdx.x + it * THREADS;
        if (it < 6 || idx < CHUNK_ELEMS) {
            const unsigned int dv = idx & (DVEC - 1);
            const int off = srcoff[idx >> 4];
            float4 v = make_float4(0.f, 0.f, 0.f, 0.f);
            if (off >= 0) v = __ldg(in + (unsigned)off + dv);
            tile[idx] = v;
        }
    }

    asm volatile("fence.proxy.async.shared::cta;" ::: "memory");
    __syncthreads();

    // Phase 3: one bulk store for the whole contiguous 25 KB chunk.
    if (threadIdx.x == 0) {
        uint32_t saddr;
        asm("{ .reg .u64 t; cvta.to.shared.u64 t, %1; cvt.u32.u64 %0, t; }"
            : "=r"(saddr) : "l"(tile));
        const float4* dst = out + (size_t)p0 * (KK * DVEC);
        asm volatile("cp.async.bulk.global.shared::cta.bulk_group [%0], [%1], %2;"
            :: "l"(dst), "r"(saddr), "r"((unsigned)CHUNK_BYTES) : "memory");
        asm volatile("cp.async.bulk.commit_group;" ::: "memory");
        // SMEM must remain valid until the bulk engine has read it.
        asm volatile("cp.async.bulk.wait_group.read 0;" ::: "memory");
    }
}

extern "C" void kernel_launch(void* const* d_in, const int* in_sizes, int n_in,
                              void* d_out, int out_size)
{
    const float4* in = (const float4*)d_in[0];
    float4* out = (float4*)d_out;

    // total pixels = out floats / (49*64) = 36864 ; CTAs = /2 = 18432
    unsigned int npix_total = (unsigned int)(out_size / (KK * 64));
    unsigned int blocks = npix_total / CHUNK_PIX;
    local_expand_bulk2_kernel<<<blocks, THREADS>>>(in, out);
}

// round 10
// speedup vs baseline: 1.0857x; 1.0388x over previous
#include <cuda_runtime.h>

// LocalExpansion via scatter, stores emitted in ascending destination-address
// order (best DRAM row-buffer locality). out[q,k,dv] = in[q+shift(k),dv],
// 7x7 window, zero-padded.
//
// Thread (bh, y, x, dv) loads its 16B slice once and scatters it to the 49
// destinations q = p - shift(k), tap k. Destination address offset is
// -(shift)*ROWV + k*DVEC, dominated by -shift, so iterating the shift
// DESCENDING (i = 6..0, j = 6..0) makes the 49 store addresses monotonically
// increasing. Zero-fill of own-row OOB taps rides the same loop.
//
// B*H = 16, N = 48*48 = 2304, K = 49, D = 64 floats (= 16 float4).

#define HEIGHT 48
#define WIDTH  48
#define NPIX   (HEIGHT * WIDTH)   // 2304
#define KK     49
#define DVEC   16                 // float4 per tap
#define ROWV   (KK * DVEC)        // 784 float4 per output pixel row

__global__ void __launch_bounds__(256) local_scatter_sorted_kernel(
    const float4* __restrict__ in, float4* __restrict__ out)
{
    // blockDim = 256 = 16 dv * 16 x-pixels ; gridDim = (3, 48, 16)
    const int dv = (int)(threadIdx.x & 15u);
    const int x  = (int)(blockIdx.x * 16u + (threadIdx.x >> 4));
    const int y  = (int)blockIdx.y;
    const int bh = (int)blockIdx.z;

    const unsigned int p = (unsigned)bh * NPIX + (unsigned)(y * WIDTH + x);

    const float4 v = __ldg(in + (size_t)p * DVEC + dv);
    float4* __restrict__ base = out + (size_t)p * ROWV + dv;

    if ((unsigned)(y - 3) < (unsigned)(HEIGHT - 6) &&
        (unsigned)(x - 3) < (unsigned)(WIDTH - 6)) {
        // Interior: all 49 destinations valid; descending shift order =>
        // ascending destination addresses.
        #pragma unroll
        for (int i = 6; i >= 0; --i) {
            #pragma unroll
            for (int j = 6; j >= 0; --j) {
                const int k = i * 7 + j;
                const int off = -(((i - 3) * WIDTH) + (j - 3)) * ROWV + k * DVEC;
                __stcs(base + off, v);
            }
        }
    } else {
        const float4 z = make_float4(0.f, 0.f, 0.f, 0.f);
        #pragma unroll
        for (int i = 6; i >= 0; --i) {
            const bool src_yok = (unsigned)(y + (i - 3)) < (unsigned)HEIGHT;
            const bool dst_yok = (unsigned)(y - (i - 3)) < (unsigned)HEIGHT;
            #pragma unroll
            for (int j = 6; j >= 0; --j) {
                const int k = i * 7 + j;
                const bool dst_ok = dst_yok && ((unsigned)(x - (j - 3)) < (unsigned)WIDTH);
                const bool src_ok = src_yok && ((unsigned)(x + (j - 3)) < (unsigned)WIDTH);

                const int off = -(((i - 3) * WIDTH) + (j - 3)) * ROWV + k * DVEC;
                if (dst_ok) __stcs(base + off, v);        // scatter my value
                if (!src_ok) __stcs(base + k * DVEC, z);  // zero-fill my OOB tap
            }
        }
    }
}

extern "C" void kernel_launch(void* const* d_in, const int* in_sizes, int n_in,
                              void* d_out, int out_size)
{
    const float4* in = (const float4*)d_in[0];
    float4* out = (float4*)d_out;
    (void)out_size;

    dim3 grid(WIDTH / 16, HEIGHT, 16);   // (3, 48, 16) -> 2304 CTAs
    local_scatter_sorted_kernel<<<grid, 256>>>(in, out);
}